// round 5
// baseline (speedup 1.0000x reference)
#include <cuda_runtime.h>

#define BATCH 8
#define INPUT_SIZE 8192
#define HIDDEN_SIZE 8192
#define OUTPUT_SIZE 2048
#define KDIM 16384

#define SLICE  1024
#define SLICE4 (SLICE / 4)            // 256 float4 per batch per slice
#define NSPLIT1 (KDIM / SLICE)        // 16
#define NSPLIT2 (HIDDEN_SIZE / SLICE) // 8
#define TILES1 (HIDDEN_SIZE / 64)     // 128 row tiles (64 rows/block, 512 thr)
#define TILES2 (OUTPUT_SIZE / 16)     // 128 row tiles (16 rows/block, 256 thr)
#define NITER  (SLICE4 / 32)          // 8 k-strips per slice

typedef unsigned long long u64;

// Scratch (allocation-free)
__device__ float g_part1[NSPLIT1][BATCH][HIDDEN_SIZE];  // 4 MB
__device__ float g_hidden[BATCH][HIDDEN_SIZE];          // 256 KB
__device__ float g_part2[NSPLIT2][BATCH][OUTPUT_SIZE];  // 512 KB

// --------------------------------------------------------------------------
__device__ __forceinline__ void fma2(u64& d, u64 a, u64 b) {
    asm("fma.rn.f32x2 %0, %1, %2, %0;" : "+l"(d) : "l"(a), "l"(b));
}
__device__ __forceinline__ void ldg_cs_u64x2(u64& a, u64& b, const void* p) {
    asm volatile("ld.global.cs.v2.u64 {%0,%1}, [%2];"
                 : "=l"(a), "=l"(b) : "l"(p));
}
__device__ __forceinline__ float pair_sum(u64 v) {
    return __uint_as_float((unsigned)v) + __uint_as_float((unsigned)(v >> 32));
}

// ==========================================================================
// Kernel 1: partial GEMV. Block = (tile, split): 64 rows x 1024-K slice.
// 512 threads, 1 block/SM, 4 rows/warp. Weight prefetch starts BEFORE the
// staging barrier; inner loop is barrier-free with register double-buffer.
// ==========================================================================
__global__ __launch_bounds__(512, 1)
void rnn_i2h_kernel(const float* __restrict__ x,
                    const float* __restrict__ h0,
                    const float* __restrict__ W)     // [HIDDEN, KDIM]
{
    __shared__ float4 s_in[BATCH][SLICE4];   // 32 KB

    const int tid   = threadIdx.x;
    const int lane  = tid & 31;
    const int warp  = tid >> 5;                   // 0..15
    const int tile  = blockIdx.x & (TILES1 - 1);  // 0..127
    const int split = blockIdx.x >> 7;            // 0..15
    const int row0  = tile * 64 + warp * 4;

    const char* wp[4];
    #pragma unroll
    for (int r = 0; r < 4; r++)
        wp[r] = (const char*)(W + (size_t)(row0 + r) * KDIM + split * SLICE);

    u64 w0[4][2], w1[4][2];

    auto ldw = [&](u64 (&wb)[4][2], int kk) {
        const size_t off = (size_t)(kk * 32 + lane) * 16;
        #pragma unroll
        for (int r = 0; r < 4; r++)
            ldg_cs_u64x2(wb[r][0], wb[r][1], wp[r] + off);
    };

    // ---- issue first weight strip BEFORE staging (overlaps DRAM with L2) --
    ldw(w0, 0);

    // ---- stage input slice: 8 batches x 1024 floats (2048 float4 / 512t) --
    const float* src = (split < NSPLIT1 / 2)
                         ? (x  + split * SLICE)
                         : (h0 + (split - NSPLIT1 / 2) * SLICE);
    #pragma unroll
    for (int t = 0; t < 4; ++t) {
        int f  = tid + t * 512;
        int b  = f >> 8;
        int k4 = f & (SLICE4 - 1);
        s_in[b][k4] = ((const float4*)(src + (size_t)b * INPUT_SIZE))[k4];
    }
    __syncthreads();        // only barrier

    u64 acc[4][BATCH];
    #pragma unroll
    for (int r = 0; r < 4; r++)
        #pragma unroll
        for (int b = 0; b < BATCH; b++)
            acc[r][b] = 0ull;

    auto step = [&](u64 (&wb)[4][2], int kk) {
        const int k4v = kk * 32 + lane;
        #pragma unroll
        for (int b = 0; b < BATCH; b++) {
            const u64* v = reinterpret_cast<const u64*>(&s_in[b][k4v]);
            u64 va = v[0], vb = v[1];
            #pragma unroll
            for (int r = 0; r < 4; r++) {
                fma2(acc[r][b], wb[r][0], va);
                fma2(acc[r][b], wb[r][1], vb);
            }
        }
    };

    #pragma unroll
    for (int i = 0; i < NITER; i += 2) {
        ldw(w1, i + 1);          // keep next strip in flight during compute
        step(w0, i);
        if (i + 2 < NITER) ldw(w0, i + 2);
        step(w1, i + 1);
    }

    #pragma unroll
    for (int r = 0; r < 4; r++) {
        #pragma unroll
        for (int b = 0; b < BATCH; b++) {
            float s = pair_sum(acc[r][b]);
            #pragma unroll
            for (int off = 16; off > 0; off >>= 1)
                s += __shfl_xor_sync(0xffffffffu, s, off);
            if (lane == b)
                g_part1[split][b][row0 + r] = s;
        }
    }
}

// ==========================================================================
// Reduce 1: hidden = tanh(sum_16 part1 + bias)   (float4 vectorized)
// ==========================================================================
__global__ void rnn_reduce1_kernel(const float* __restrict__ bias)
{
    int idx = blockIdx.x * 256 + threadIdx.x;       // 16384 float4s
    int b  = idx >> 11;
    int h4 = idx & (HIDDEN_SIZE / 4 - 1);
    float4 a = ((const float4*)bias)[h4];
    #pragma unroll
    for (int s = 0; s < NSPLIT1; s++) {
        float4 p = ((const float4*)&g_part1[s][b][0])[h4];
        a.x += p.x; a.y += p.y; a.z += p.z; a.w += p.w;
    }
    float4 r = make_float4(tanhf(a.x), tanhf(a.y), tanhf(a.z), tanhf(a.w));
    ((float4*)&g_hidden[b][0])[h4] = r;
}

// ==========================================================================
// Kernel 2: partial GEMV for output. 256 thr, 2 rows/warp, prefetched.
// ==========================================================================
__global__ __launch_bounds__(256, 2)
void rnn_h2o_kernel(const float* __restrict__ W2)   // [OUT, HIDDEN]
{
    __shared__ float4 s_in[BATCH][SLICE4];   // 32 KB

    const int tid   = threadIdx.x;
    const int lane  = tid & 31;
    const int warp  = tid >> 5;
    const int tile  = blockIdx.x & (TILES2 - 1);
    const int split = blockIdx.x >> 7;
    const int row0  = tile * 16 + warp * 2;

    const char* wp[2];
    #pragma unroll
    for (int r = 0; r < 2; r++)
        wp[r] = (const char*)(W2 + (size_t)(row0 + r) * HIDDEN_SIZE + split * SLICE);

    u64 w0[2][2], w1[2][2];

    auto ldw = [&](u64 (&wb)[2][2], int kk) {
        const size_t off = (size_t)(kk * 32 + lane) * 16;
        #pragma unroll
        for (int r = 0; r < 2; r++)
            ldg_cs_u64x2(wb[r][0], wb[r][1], wp[r] + off);
    };

    ldw(w0, 0);   // before staging barrier

    const float* src = &g_hidden[0][0] + split * SLICE;
    #pragma unroll
    for (int t = 0; t < 8; ++t) {
        int f  = tid + t * 256;
        int b  = f >> 8;
        int k4 = f & (SLICE4 - 1);
        s_in[b][k4] = ((const float4*)(src + (size_t)b * HIDDEN_SIZE))[k4];
    }
    __syncthreads();

    u64 acc[2][BATCH];
    #pragma unroll
    for (int r = 0; r < 2; r++)
        #pragma unroll
        for (int b = 0; b < BATCH; b++)
            acc[r][b] = 0ull;

    auto step = [&](u64 (&wb)[2][2], int kk) {
        const int k4v = kk * 32 + lane;
        #pragma unroll
        for (int b = 0; b < BATCH; b++) {
            const u64* v = reinterpret_cast<const u64*>(&s_in[b][k4v]);
            u64 va = v[0], vb = v[1];
            #pragma unroll
            for (int r = 0; r < 2; r++) {
                fma2(acc[r][b], wb[r][0], va);
                fma2(acc[r][b], wb[r][1], vb);
            }
        }
    };

    #pragma unroll
    for (int i = 0; i < NITER; i += 2) {
        ldw(w1, i + 1);
        step(w0, i);
        if (i + 2 < NITER) ldw(w0, i + 2);
        step(w1, i + 1);
    }

    #pragma unroll
    for (int r = 0; r < 2; r++) {
        #pragma unroll
        for (int b = 0; b < BATCH; b++) {
            float s = pair_sum(acc[r][b]);
            #pragma unroll
            for (int off = 16; off > 0; off >>= 1)
                s += __shfl_xor_sync(0xffffffffu, s, off);
            if (lane == b)
                g_part2[split][b][row0 + r] = s;
        }
    }
}

// ==========================================================================
// Reduce 2: out = sum_8 part2 + bias2   (float4 vectorized)
// ==========================================================================
__global__ void rnn_reduce2_kernel(const float* __restrict__ bias2,
                                   float* __restrict__ out)
{
    int idx = blockIdx.x * 128 + threadIdx.x;       // 4096 float4s
    int b  = idx >> 9;
    int o4 = idx & (OUTPUT_SIZE / 4 - 1);
    float4 a = ((const float4*)bias2)[o4];
    #pragma unroll
    for (int s = 0; s < NSPLIT2; s++) {
        float4 p = ((const float4*)&g_part2[s][b][0])[o4];
        a.x += p.x; a.y += p.y; a.z += p.z; a.w += p.w;
    }
    ((float4*)out)[idx] = a;
}

// --------------------------------------------------------------------------
// Inputs: x, initial_hidden, i2h_weight, i2h_bias, h2o_weight, h2o_bias
// --------------------------------------------------------------------------
extern "C" void kernel_launch(void* const* d_in, const int* in_sizes, int n_in,
                              void* d_out, int out_size) {
    const float* x  = (const float*)d_in[0];
    const float* h0 = (const float*)d_in[1];
    const float* W1 = (const float*)d_in[2];
    const float* b1 = (const float*)d_in[3];
    const float* W2 = (const float*)d_in[4];
    const float* b2 = (const float*)d_in[5];
    float* out      = (float*)d_out;

    rnn_i2h_kernel<<<TILES1 * NSPLIT1, 512>>>(x, h0, W1);
    rnn_reduce1_kernel<<<(BATCH * HIDDEN_SIZE / 4) / 256, 256>>>(b1);
    rnn_h2o_kernel<<<TILES2 * NSPLIT2, 256>>>(W2);
    rnn_reduce2_kernel<<<(BATCH * OUTPUT_SIZE / 4) / 128, 128>>>(b2, out);
}

// round 6
// speedup vs baseline: 1.0296x; 1.0296x over previous
#include <cuda_runtime.h>

#define BATCH 8
#define INPUT_SIZE 8192
#define HIDDEN_SIZE 8192
#define OUTPUT_SIZE 2048
#define KDIM 16384

typedef unsigned long long u64;

// Intermediate hidden activations (8 x 8192 fp32 = 256 KB).
__device__ float g_hidden[BATCH * HIDDEN_SIZE];
// Partial sums for the K-split h2o GEMV: [split][batch][out]
__device__ float g_part[2][BATCH][OUTPUT_SIZE];

// ---------------------------------------------------------------------------
// cp.async helpers (16B variant)
// ---------------------------------------------------------------------------
__device__ __forceinline__ void cp_async16(void* smem_dst, const void* gmem_src) {
    unsigned s = (unsigned)__cvta_generic_to_shared(smem_dst);
    asm volatile("cp.async.cg.shared.global [%0], [%1], 16;\n" :: "r"(s), "l"(gmem_src));
}
__device__ __forceinline__ void cp_commit()  { asm volatile("cp.async.commit_group;\n"); }
__device__ __forceinline__ void cp_wait1()   { asm volatile("cp.async.wait_group 1;\n"); }
__device__ __forceinline__ void cp_wait0()   { asm volatile("cp.async.wait_group 0;\n"); }

// Packed dual-FMA: d.lo += a.lo*b.lo ; d.hi += a.hi*b.hi  (halves FFMA issue)
__device__ __forceinline__ void fma2(u64& d, u64 a, u64 b) {
    asm("fma.rn.f32x2 %0, %1, %2, %0;" : "+l"(d) : "l"(a), "l"(b));
}
// 16B streaming global load into two packed u64
__device__ __forceinline__ void ldg_cs_u64x2(u64& a, u64& b, const void* p) {
    asm volatile("ld.global.cs.v2.u64 {%0,%1}, [%2];"
                 : "=l"(a), "=l"(b) : "l"(p));
}
__device__ __forceinline__ float pair_sum(u64 v) {
    return __uint_as_float((unsigned)v) + __uint_as_float((unsigned)(v >> 32));
}

#define TK  512
#define TK4 (TK / 4)    // 128 float4 per batch per chunk

// ===========================================================================
// Kernel 1: hidden[b,h] = tanh( x[b,:]·W[h,0:8192] + h0[b,:]·W[h,8192:] + b1[h] )
// 256 threads (8 warps), 4 rows/warp -> 32 rows/block, grid = 256. Full K per
// block. cp.async double-buffered input staging; f32x2 packed FMA.
// ===========================================================================
#define R1 4
#define ROWS_PER_BLOCK_1 (R1 * 8)   // 32

__global__ __launch_bounds__(256, 2)
void rnn_i2h_kernel(const float* __restrict__ x,
                    const float* __restrict__ h0,
                    const float* __restrict__ W,      // [HIDDEN_SIZE, KDIM]
                    const float* __restrict__ bias)
{
    __shared__ float4 s_in[2][BATCH][TK4];   // 2 x 16 KB

    const int tid  = threadIdx.x;
    const int lane = tid & 31;
    const int warp = tid >> 5;
    const int row0 = blockIdx.x * ROWS_PER_BLOCK_1 + warp * R1;

    const int NCHUNK = KDIM / TK;          // 32
    const int XCHUNK = INPUT_SIZE / TK;    // 16

    u64 acc[R1][BATCH];
    #pragma unroll
    for (int r = 0; r < R1; r++)
        #pragma unroll
        for (int b = 0; b < BATCH; b++)
            acc[r][b] = 0ull;

    const char* wp[R1];
    #pragma unroll
    for (int r = 0; r < R1; r++)
        wp[r] = (const char*)(W + (size_t)(row0 + r) * KDIM);

    auto stage = [&](int c, int buf) {
        const float* src = (c < XCHUNK) ? (x + c * TK)
                                        : (h0 + (c - XCHUNK) * TK);
        #pragma unroll
        for (int t = 0; t < 4; ++t) {
            int f  = tid + t * 256;
            int b  = f >> 7;            // / TK4 (=128)
            int k4 = f & (TK4 - 1);
            cp_async16(&s_in[buf][b][k4],
                       (const float4*)(src + (size_t)b * INPUT_SIZE) + k4);
        }
        cp_commit();
    };

    stage(0, 0);

    for (int c = 0; c < NCHUNK; ++c) {
        const int buf = c & 1;
        __syncthreads();                     // buffer (c+1)&1 free
        if (c + 1 < NCHUNK) { stage(c + 1, buf ^ 1); cp_wait1(); }
        else                { cp_wait0(); }
        __syncthreads();                     // chunk c visible

        const size_t cbase = (size_t)c * TK * 4;   // byte offset of chunk

        #pragma unroll
        for (int i = 0; i < TK4 / 32; ++i) {       // 4 strips
            const int k4 = i * 32 + lane;
            u64 w[R1][2];
            #pragma unroll
            for (int r = 0; r < R1; r++)
                ldg_cs_u64x2(w[r][0], w[r][1], wp[r] + cbase + (size_t)k4 * 16);

            #pragma unroll
            for (int b = 0; b < BATCH; b++) {
                const u64* v = reinterpret_cast<const u64*>(&s_in[buf][b][k4]);
                u64 va = v[0], vb = v[1];
                #pragma unroll
                for (int r = 0; r < R1; r++) {
                    fma2(acc[r][b], w[r][0], va);
                    fma2(acc[r][b], w[r][1], vb);
                }
            }
        }
    }

    // warp butterfly reduction (once per block — amortized over full K)
    #pragma unroll
    for (int r = 0; r < R1; r++) {
        #pragma unroll
        for (int b = 0; b < BATCH; b++) {
            float s = pair_sum(acc[r][b]);
            #pragma unroll
            for (int off = 16; off > 0; off >>= 1)
                s += __shfl_xor_sync(0xffffffffu, s, off);
            if (lane == b) {
                const int row = row0 + r;
                g_hidden[b * HIDDEN_SIZE + row] = tanhf(s + __ldg(bias + row));
            }
        }
    }
}

// ===========================================================================
// Kernel 2: K-split GEMV. part[s][b,o] = hidden[b, s*4096:(s+1)*4096]·W2[o,...]
// 256 threads, 2 rows/warp -> 16 rows/block, grid = 128 tiles x 2 splits.
// ===========================================================================
#define R2 2
#define ROWS_PER_BLOCK_2 (R2 * 8)   // 16
#define KSPLIT 2
#define KHALF (HIDDEN_SIZE / KSPLIT)   // 4096

__global__ __launch_bounds__(256, 2)
void rnn_h2o_kernel(const float* __restrict__ W2)   // [OUTPUT_SIZE, HIDDEN_SIZE]
{
    __shared__ float4 s_in[2][BATCH][TK4];   // 2 x 16 KB

    const int tid  = threadIdx.x;
    const int lane = tid & 31;
    const int warp = tid >> 5;
    const int tile = blockIdx.x & 127;
    const int half = blockIdx.x >> 7;
    const int row0 = tile * ROWS_PER_BLOCK_2 + warp * R2;
    const int kbase = half * KHALF;

    const int NCHUNK = KHALF / TK;   // 8

    u64 acc[R2][BATCH];
    #pragma unroll
    for (int r = 0; r < R2; r++)
        #pragma unroll
        for (int b = 0; b < BATCH; b++)
            acc[r][b] = 0ull;

    auto stage = [&](int c, int buf) {
        const float* src = g_hidden + kbase + c * TK;
        #pragma unroll
        for (int t = 0; t < 4; ++t) {
            int f  = tid + t * 256;
            int b  = f >> 7;
            int k4 = f & (TK4 - 1);
            cp_async16(&s_in[buf][b][k4],
                       (const float4*)(src + (size_t)b * HIDDEN_SIZE) + k4);
        }
        cp_commit();
    };

    stage(0, 0);

    const char* wp0 = (const char*)(W2 + (size_t)(row0 + 0) * HIDDEN_SIZE + kbase);
    const char* wp1 = (const char*)(W2 + (size_t)(row0 + 1) * HIDDEN_SIZE + kbase);

    for (int c = 0; c < NCHUNK; ++c) {
        const int buf = c & 1;
        __syncthreads();
        if (c + 1 < NCHUNK) { stage(c + 1, buf ^ 1); cp_wait1(); }
        else                { cp_wait0(); }
        __syncthreads();

        const size_t cbase = (size_t)c * TK * 4;

        #pragma unroll
        for (int i = 0; i < TK4 / 32; ++i) {
            const int k4 = i * 32 + lane;
            u64 w0a, w0b, w1a, w1b;
            ldg_cs_u64x2(w0a, w0b, wp0 + cbase + (size_t)k4 * 16);
            ldg_cs_u64x2(w1a, w1b, wp1 + cbase + (size_t)k4 * 16);

            #pragma unroll
            for (int b = 0; b < BATCH; b++) {
                const u64* v = reinterpret_cast<const u64*>(&s_in[buf][b][k4]);
                u64 va = v[0], vb = v[1];
                fma2(acc[0][b], w0a, va);
                fma2(acc[0][b], w0b, vb);
                fma2(acc[1][b], w1a, va);
                fma2(acc[1][b], w1b, vb);
            }
        }
    }

    #pragma unroll
    for (int r = 0; r < R2; r++) {
        #pragma unroll
        for (int b = 0; b < BATCH; b++) {
            float s = pair_sum(acc[r][b]);
            #pragma unroll
            for (int off = 16; off > 0; off >>= 1)
                s += __shfl_xor_sync(0xffffffffu, s, off);
            if (lane == b)
                g_part[half][b][row0 + r] = s;
        }
    }
}

// ===========================================================================
// Kernel 3: out[b,o] = part[0][b,o] + part[1][b,o] + bias2[o]  (float4)
// ===========================================================================
__global__ void rnn_reduce_kernel(const float* __restrict__ bias2,
                                  float* __restrict__ out)
{
    int idx = blockIdx.x * 128 + threadIdx.x;   // 4096 float4s
    int b  = idx >> 9;                           // / (OUT/4)
    int o4 = idx & (OUTPUT_SIZE / 4 - 1);
    float4 a  = ((const float4*)bias2)[o4];
    float4 p0 = ((const float4*)&g_part[0][b][0])[o4];
    float4 p1 = ((const float4*)&g_part[1][b][0])[o4];
    a.x += p0.x + p1.x;  a.y += p0.y + p1.y;
    a.z += p0.z + p1.z;  a.w += p0.w + p1.w;
    ((float4*)out)[idx] = a;
}

// ---------------------------------------------------------------------------
// Inputs: x, initial_hidden, i2h_weight, i2h_bias, h2o_weight, h2o_bias
// ---------------------------------------------------------------------------
extern "C" void kernel_launch(void* const* d_in, const int* in_sizes, int n_in,
                              void* d_out, int out_size) {
    const float* x  = (const float*)d_in[0];
    const float* h0 = (const float*)d_in[1];
    const float* W1 = (const float*)d_in[2];
    const float* b1 = (const float*)d_in[3];
    const float* W2 = (const float*)d_in[4];
    const float* b2 = (const float*)d_in[5];
    float* out      = (float*)d_out;

    rnn_i2h_kernel<<<HIDDEN_SIZE / ROWS_PER_BLOCK_1, 256>>>(x, h0, W1, b1);
    rnn_h2o_kernel<<<(OUTPUT_SIZE / ROWS_PER_BLOCK_2) * KSPLIT, 256>>>(W2);
    rnn_reduce_kernel<<<(BATCH * OUTPUT_SIZE / 4) / 128, 128>>>(b2, out);
}